// round 3
// baseline (speedup 1.0000x reference)
#include <cuda_runtime.h>

// ---------------------------------------------------------------------------
// EdgeNetwork via per-node factorization + f32x2 packed edge MLP.
//   pre_k : xs[n] = x[n]@W1a + b1 + vp[batch[n]]@W1c ; xb[n] = x[n]@W1b
//   edge_k: h = xs[s]+xb[d]; 3x(LN+tanh), H=8, all packed f32x2 in regs.
// ---------------------------------------------------------------------------

#define NODE_CAP 131072
typedef unsigned long long u64;

__device__ __align__(16) float g_xs[NODE_CAP * 8];
__device__ __align__(16) float g_xb[NODE_CAP * 8];

// int64-vs-int32 detection from bit pattern (odd words all zero => int64).
__device__ __forceinline__ int detect_is64(const int* __restrict__ ei) {
    int nz = 0;
#pragma unroll
    for (int i = 1; i < 16; i += 2) nz |= ei[i];
    return nz == 0;
}

// ---- f32x2 packed helpers (sm_103a FFMA2 path) -----------------------------
__device__ __forceinline__ u64 pack2(float lo, float hi) {
    u64 r; asm("mov.b64 %0,{%1,%2};" : "=l"(r) : "f"(lo), "f"(hi)); return r;
}
__device__ __forceinline__ float2 unpack2(u64 v) {
    float2 f; asm("mov.b64 {%0,%1},%2;" : "=f"(f.x), "=f"(f.y) : "l"(v)); return f;
}
__device__ __forceinline__ u64 fma2(u64 a, u64 b, u64 c) {
    u64 d; asm("fma.rn.f32x2 %0,%1,%2,%3;" : "=l"(d) : "l"(a), "l"(b), "l"(c)); return d;
}
__device__ __forceinline__ u64 add2(u64 a, u64 b) {
    u64 d; asm("add.rn.f32x2 %0,%1,%2;" : "=l"(d) : "l"(a), "l"(b)); return d;
}
__device__ __forceinline__ u64 mul2(u64 a, u64 b) {
    u64 d; asm("mul.rn.f32x2 %0,%1,%2;" : "=l"(d) : "l"(a), "l"(b)); return d;
}

// ---------------------------------------------------------------------------
// Per-node precompute (scalar; ~3us, not the bottleneck)
// ---------------------------------------------------------------------------
__global__ void __launch_bounds__(256) pre_k(
    const float* __restrict__ x, const int* __restrict__ batch_raw,
    const float* __restrict__ vp, const float* __restrict__ W1,
    const float* __restrict__ b1, const int* __restrict__ ei, int N, int G)
{
    __shared__ float sW1[48 * 8];
    __shared__ float svp[64 * 16];
    __shared__ float sb1[8];
    __shared__ int sflag;
    int t = threadIdx.x;
    if (t == 0) sflag = detect_is64(ei);
    for (int i = t; i < 384; i += blockDim.x) sW1[i] = W1[i];
    int gv = G * 16; if (gv > 1024) gv = 1024;
    for (int i = t; i < gv; i += blockDim.x) svp[i] = vp[i];
    if (t < 8) sb1[t] = b1[t];
    __syncthreads();

    int n = blockIdx.x * blockDim.x + t;
    if (n >= N) return;

    int g = sflag ? batch_raw[2 * n] : batch_raw[n];

    float xi[16];
    const float* xr = x + (size_t)n * 16;
#pragma unroll
    for (int k = 0; k < 16; k += 4) {
        float4 v = *(const float4*)(xr + k);
        xi[k] = v.x; xi[k + 1] = v.y; xi[k + 2] = v.z; xi[k + 3] = v.w;
    }
    const float* vg = svp + g * 16;

    float xs[8], xb[8];
#pragma unroll
    for (int j = 0; j < 8; j++) {
        float a = sb1[j];
        float b = 0.0f;
#pragma unroll
        for (int k = 0; k < 16; k++) {
            a = fmaf(xi[k], sW1[k * 8 + j], a);
            a = fmaf(vg[k], sW1[(32 + k) * 8 + j], a);
            b = fmaf(xi[k], sW1[(16 + k) * 8 + j], b);
        }
        xs[j] = a; xb[j] = b;
    }
    float4* o1 = (float4*)(g_xs + (size_t)n * 8);
    o1[0] = make_float4(xs[0], xs[1], xs[2], xs[3]);
    o1[1] = make_float4(xs[4], xs[5], xs[6], xs[7]);
    float4* o2 = (float4*)(g_xb + (size_t)n * 8);
    o2[0] = make_float4(xb[0], xb[1], xb[2], xb[3]);
    o2[1] = make_float4(xb[4], xb[5], xb[6], xb[7]);
}

// ---------------------------------------------------------------------------
// LN + tanh on 4 f32x2 pairs -> 8 scalar tanh outputs.
// tanh(z) = 1 - 2/(e^{2z}+1); two reciprocals share one rcp via product trick.
// ---------------------------------------------------------------------------
__device__ __forceinline__ void ln_tanh_p(
    const u64 hp[4], const u64* __restrict__ gp, const u64* __restrict__ bep,
    float t[8])
{
    u64 s2  = add2(add2(hp[0], hp[1]), add2(hp[2], hp[3]));
    u64 ss2 = fma2(hp[0], hp[0], fma2(hp[1], hp[1],
              fma2(hp[2], hp[2], mul2(hp[3], hp[3]))));
    float2 sf = unpack2(s2), ssf = unpack2(ss2);
    float mu  = (sf.x + sf.y) * 0.125f;
    float ss  = (ssf.x + ssf.y) * 0.125f;
    float var = fmaf(-mu, mu, ss);
    float r   = rsqrtf(var + 1e-5f);

    u64 mun = pack2(-mu, -mu);
    u64 rd  = pack2(r, r);
#pragma unroll
    for (int p = 0; p < 4; p++) {
        u64 Ap = mul2(rd, gp[p]);
        u64 zp = fma2(add2(hp[p], mun), Ap, bep[p]);
        float2 z = unpack2(zp);
        float ea, eb, rp;
        asm("ex2.approx.f32 %0, %1;" : "=f"(ea) : "f"(z.x * 2.885390081777927f));
        asm("ex2.approx.f32 %0, %1;" : "=f"(eb) : "f"(z.y * 2.885390081777927f));
        float eap = ea + 1.0f, ebp = eb + 1.0f;
        asm("rcp.approx.f32 %0, %1;" : "=f"(rp) : "f"(eap * ebp));
        t[2 * p]     = fmaf(-2.0f * ebp, rp, 1.0f);   // 1 - 2/eap
        t[2 * p + 1] = fmaf(-2.0f * eap, rp, 1.0f);   // 1 - 2/ebp
    }
}

// 8->8 GEMM, outputs as 4 f32x2 pairs. wp: [k][pair] u64 view of row-major W.
__device__ __forceinline__ void gemm8(
    const float t[8], const u64* __restrict__ wp, const u64* __restrict__ bp,
    u64 acc[4])
{
    u64 td[8];
#pragma unroll
    for (int k = 0; k < 8; k++) td[k] = pack2(t[k], t[k]);
#pragma unroll
    for (int p = 0; p < 4; p++) {
        u64 a = fma2(td[0], wp[p], bp[p]);
#pragma unroll
        for (int k = 1; k < 8; k++) a = fma2(td[k], wp[k * 4 + p], a);
        acc[p] = a;
    }
}

__global__ void __launch_bounds__(256, 3) edge_k(
    const int* __restrict__ ei, int E,
    const float* __restrict__ g1, const float* __restrict__ be1,
    const float* __restrict__ W2, const float* __restrict__ b2,
    const float* __restrict__ g2, const float* __restrict__ be2,
    const float* __restrict__ W3, const float* __restrict__ b3,
    const float* __restrict__ g3, const float* __restrict__ be3,
    const float* __restrict__ W4, const float* __restrict__ b4,
    float* __restrict__ out)
{
    __shared__ u64 sW2p[32], sW3p[32], sW4p[4];
    __shared__ u64 sg1p[4], sbe1p[4], sb2p[4], sg2p[4], sbe2p[4];
    __shared__ u64 sb3p[4], sg3p[4], sbe3p[4];
    __shared__ float sb4;
    __shared__ int sflag;

    int t = threadIdx.x;
    if (t == 0) { sflag = detect_is64(ei); sb4 = b4[0]; }
    if (t < 32) {
        sW2p[t] = ((const u64*)W2)[t];
        sW3p[t] = ((const u64*)W3)[t];
    }
    if (t < 4) {
        sW4p[t]  = ((const u64*)W4)[t];
        sg1p[t]  = ((const u64*)g1)[t];
        sbe1p[t] = ((const u64*)be1)[t];
        sb2p[t]  = ((const u64*)b2)[t];
        sg2p[t]  = ((const u64*)g2)[t];
        sbe2p[t] = ((const u64*)be2)[t];
        sb3p[t]  = ((const u64*)b3)[t];
        sg3p[t]  = ((const u64*)g3)[t];
        sbe3p[t] = ((const u64*)be3)[t];
    }
    __syncthreads();

    int is64 = sflag;
    int stride = gridDim.x * blockDim.x;
    for (int e = blockIdx.x * blockDim.x + t; e < E; e += stride) {
        int s, d;
        if (is64) {
            s = ei[2 * (size_t)e];
            d = ei[2 * ((size_t)E + e)];
        } else {
            s = ei[e]; d = ei[E + e];
        }

        const ulonglong2* ap = (const ulonglong2*)(g_xs + (size_t)s * 8);
        const ulonglong2* bq = (const ulonglong2*)(g_xb + (size_t)d * 8);
        ulonglong2 A0 = ap[0], A1 = ap[1];
        ulonglong2 B0 = bq[0], B1 = bq[1];

        u64 hp[4] = { add2(A0.x, B0.x), add2(A0.y, B0.y),
                      add2(A1.x, B1.x), add2(A1.y, B1.y) };

        float tv[8];
        ln_tanh_p(hp, sg1p, sbe1p, tv);
        u64 h2[4]; gemm8(tv, sW2p, sb2p, h2);
        ln_tanh_p(h2, sg2p, sbe2p, tv);
        u64 h3[4]; gemm8(tv, sW3p, sb3p, h3);
        ln_tanh_p(h3, sg3p, sbe3p, tv);

        u64 o2 = fma2(pack2(tv[0], tv[1]), sW4p[0],
                 fma2(pack2(tv[2], tv[3]), sW4p[1],
                 fma2(pack2(tv[4], tv[5]), sW4p[2],
                 mul2(pack2(tv[6], tv[7]), sW4p[3]))));
        float2 of = unpack2(o2);
        out[e] = sb4 + of.x + of.y;
    }
}

// ---------------------------------------------------------------------------
extern "C" void kernel_launch(void* const* d_in, const int* in_sizes, int n_in,
                              void* d_out, int out_size)
{
    const float* x     = (const float*)d_in[0];
    const int*   ei    = (const int*)d_in[1];
    const float* vp    = (const float*)d_in[2];
    const int*   batch = (const int*)d_in[3];
    const float* W1  = (const float*)d_in[4];
    const float* b1  = (const float*)d_in[5];
    const float* g1  = (const float*)d_in[6];
    const float* be1 = (const float*)d_in[7];
    const float* W2  = (const float*)d_in[8];
    const float* b2  = (const float*)d_in[9];
    const float* g2  = (const float*)d_in[10];
    const float* be2 = (const float*)d_in[11];
    const float* W3  = (const float*)d_in[12];
    const float* b3  = (const float*)d_in[13];
    const float* g3  = (const float*)d_in[14];
    const float* be3 = (const float*)d_in[15];
    const float* W4  = (const float*)d_in[16];
    const float* b4  = (const float*)d_in[17];

    int N = in_sizes[0] / 16;
    int E = in_sizes[1] / 2;
    int G = in_sizes[2] / 16;

    int pb = (N + 255) / 256;
    pre_k<<<pb, 256>>>(x, batch, vp, W1, b1, ei, N, G);

    int eb = (E + 255) / 256;
    if (eb > 2368) eb = 2368;
    edge_k<<<eb, 256>>>(ei, E, g1, be1, W2, b2, g2, be2, W3, b3, g3, be3,
                        W4, b4, (float*)d_out);
}

// round 4
// speedup vs baseline: 1.9399x; 1.9399x over previous
#include <cuda_runtime.h>

// ---------------------------------------------------------------------------
// EdgeNetwork via per-node factorization. Scalar math (R2 baseline) with
// 2 edges per thread for ILP / memory-level parallelism.
//   pre_k : xs[n] = x[n]@W1a + b1 + vp[batch[n]]@W1c ; xb[n] = x[n]@W1b
//   edge_k: h = xs[s]+xb[d]; 3x(LN+tanh), H=8 in regs; 2 edges interleaved.
// ---------------------------------------------------------------------------

#define NODE_CAP 131072

__device__ __align__(16) float g_xs[NODE_CAP * 8];
__device__ __align__(16) float g_xb[NODE_CAP * 8];

// int64-vs-int32 detection from bit pattern (odd words all zero => int64).
__device__ __forceinline__ int detect_is64(const int* __restrict__ ei) {
    int nz = 0;
#pragma unroll
    for (int i = 1; i < 16; i += 2) nz |= ei[i];
    return nz == 0;
}

// ---------------------------------------------------------------------------
// Per-node precompute
// ---------------------------------------------------------------------------
__global__ void __launch_bounds__(256) pre_k(
    const float* __restrict__ x, const int* __restrict__ batch_raw,
    const float* __restrict__ vp, const float* __restrict__ W1,
    const float* __restrict__ b1, const int* __restrict__ ei, int N, int G)
{
    __shared__ float sW1[48 * 8];
    __shared__ float svp[64 * 16];
    __shared__ float sb1[8];
    __shared__ int sflag;
    int t = threadIdx.x;
    if (t == 0) sflag = detect_is64(ei);
    for (int i = t; i < 384; i += blockDim.x) sW1[i] = W1[i];
    int gv = G * 16; if (gv > 1024) gv = 1024;
    for (int i = t; i < gv; i += blockDim.x) svp[i] = vp[i];
    if (t < 8) sb1[t] = b1[t];
    __syncthreads();

    int n = blockIdx.x * blockDim.x + t;
    if (n >= N) return;

    int g = sflag ? batch_raw[2 * n] : batch_raw[n];

    float xi[16];
    const float* xr = x + (size_t)n * 16;
#pragma unroll
    for (int k = 0; k < 16; k += 4) {
        float4 v = *(const float4*)(xr + k);
        xi[k] = v.x; xi[k + 1] = v.y; xi[k + 2] = v.z; xi[k + 3] = v.w;
    }
    const float* vg = svp + g * 16;

    float xs[8], xb[8];
#pragma unroll
    for (int j = 0; j < 8; j++) {
        float a = sb1[j];
        float b = 0.0f;
#pragma unroll
        for (int k = 0; k < 16; k++) {
            a = fmaf(xi[k], sW1[k * 8 + j], a);
            a = fmaf(vg[k], sW1[(32 + k) * 8 + j], a);
            b = fmaf(xi[k], sW1[(16 + k) * 8 + j], b);
        }
        xs[j] = a; xb[j] = b;
    }
    float4* o1 = (float4*)(g_xs + (size_t)n * 8);
    o1[0] = make_float4(xs[0], xs[1], xs[2], xs[3]);
    o1[1] = make_float4(xs[4], xs[5], xs[6], xs[7]);
    float4* o2 = (float4*)(g_xb + (size_t)n * 8);
    o2[0] = make_float4(xb[0], xb[1], xb[2], xb[3]);
    o2[1] = make_float4(xb[4], xb[5], xb[6], xb[7]);
}

// ---------------------------------------------------------------------------
// tanh(z) = 1 - 2/(e^{2z}+1): MUL, EX2, ADD, RCP, FMA. LN output bounded
// (|std| <= sqrt(7)), no clamp needed.
// ---------------------------------------------------------------------------
__device__ __forceinline__ float fast_tanh(float z) {
    float q, r;
    asm("ex2.approx.f32 %0, %1;" : "=f"(q) : "f"(z * 2.885390081777927f));
    float s = q + 1.0f;
    asm("rcp.approx.f32 %0, %1;" : "=f"(r) : "f"(s));
    return fmaf(-2.0f, r, 1.0f);
}

__device__ __forceinline__ void ln_tanh(float h[8], const float* __restrict__ g,
                                        const float* __restrict__ be) {
    float s = 0.0f, ss = 0.0f;
#pragma unroll
    for (int j = 0; j < 8; j++) { s += h[j]; ss = fmaf(h[j], h[j], ss); }
    float mu = s * 0.125f;
    float var = fmaf(-mu, mu, ss * 0.125f);
    float r = rsqrtf(var + 1e-5f);
#pragma unroll
    for (int j = 0; j < 8; j++) {
        float z = fmaf((h[j] - mu) * r, g[j], be[j]);
        h[j] = fast_tanh(z);
    }
}

__device__ __forceinline__ void gemm8(const float hin[8], float hout[8],
                                      const float* __restrict__ W,
                                      const float* __restrict__ b) {
#pragma unroll
    for (int j = 0; j < 8; j++) {
        float a = b[j];
#pragma unroll
        for (int k = 0; k < 8; k++) a = fmaf(hin[k], W[k * 8 + j], a);
        hout[j] = a;
    }
}

__global__ void __launch_bounds__(128) edge_k(
    const int* __restrict__ ei, int E,
    const float* __restrict__ g1, const float* __restrict__ be1,
    const float* __restrict__ W2, const float* __restrict__ b2,
    const float* __restrict__ g2, const float* __restrict__ be2,
    const float* __restrict__ W3, const float* __restrict__ b3,
    const float* __restrict__ g3, const float* __restrict__ be3,
    const float* __restrict__ W4, const float* __restrict__ b4,
    float* __restrict__ out)
{
    __shared__ float sW2[64], sW3[64], sW4[8];
    __shared__ float sv[64];  // g1,be1,b2,g2,be2,b3,g3,be3
    __shared__ float sb4;
    __shared__ int sflag;
    int t = threadIdx.x;
    if (t == 0) { sflag = detect_is64(ei); sb4 = b4[0]; }
    if (t < 64) { sW2[t] = W2[t]; sW3[t] = W3[t]; }
    if (t < 8) {
        sW4[t] = W4[t];
        sv[t]      = g1[t];  sv[8 + t]  = be1[t];
        sv[16 + t] = b2[t];  sv[24 + t] = g2[t];  sv[32 + t] = be2[t];
        sv[40 + t] = b3[t];  sv[48 + t] = g3[t];  sv[56 + t] = be3[t];
    }
    __syncthreads();

    const float* sg1 = sv;       const float* sbe1 = sv + 8;
    const float* sb2 = sv + 16;  const float* sg2  = sv + 24; const float* sbe2 = sv + 32;
    const float* sb3 = sv + 40;  const float* sg3  = sv + 48; const float* sbe3 = sv + 56;

    int is64 = sflag;
    int tid = blockIdx.x * blockDim.x + t;
    int nthreads = gridDim.x * blockDim.x;

    for (int e0 = tid * 2; e0 < E; e0 += nthreads * 2) {
        if (e0 + 1 < E) {
            // ---- vector pair path ----
            int s0, s1, d0, d1;
            if (is64) {
                int4 sw = *(const int4*)(ei + 2 * (size_t)e0);
                int4 dw = *(const int4*)(ei + 2 * ((size_t)E + e0));
                s0 = sw.x; s1 = sw.z; d0 = dw.x; d1 = dw.z;
            } else {
                int2 sw = *(const int2*)(ei + e0);
                int2 dw = *(const int2*)(ei + (size_t)E + e0);
                s0 = sw.x; s1 = sw.y; d0 = dw.x; d1 = dw.y;
            }

            const float4* apA = (const float4*)(g_xs + (size_t)s0 * 8);
            const float4* bpA = (const float4*)(g_xb + (size_t)d0 * 8);
            const float4* apB = (const float4*)(g_xs + (size_t)s1 * 8);
            const float4* bpB = (const float4*)(g_xb + (size_t)d1 * 8);
            float4 a0A = apA[0], a1A = apA[1], c0A = bpA[0], c1A = bpA[1];
            float4 a0B = apB[0], a1B = apB[1], c0B = bpB[0], c1B = bpB[1];

            float hA[8] = { a0A.x + c0A.x, a0A.y + c0A.y, a0A.z + c0A.z, a0A.w + c0A.w,
                            a1A.x + c1A.x, a1A.y + c1A.y, a1A.z + c1A.z, a1A.w + c1A.w };
            float hB[8] = { a0B.x + c0B.x, a0B.y + c0B.y, a0B.z + c0B.z, a0B.w + c0B.w,
                            a1B.x + c1B.x, a1B.y + c1B.y, a1B.z + c1B.z, a1B.w + c1B.w };

            ln_tanh(hA, sg1, sbe1);            ln_tanh(hB, sg1, sbe1);
            float h2A[8], h2B[8];
            gemm8(hA, h2A, sW2, sb2);          gemm8(hB, h2B, sW2, sb2);
            ln_tanh(h2A, sg2, sbe2);           ln_tanh(h2B, sg2, sbe2);
            float h3A[8], h3B[8];
            gemm8(h2A, h3A, sW3, sb3);         gemm8(h2B, h3B, sW3, sb3);
            ln_tanh(h3A, sg3, sbe3);           ln_tanh(h3B, sg3, sbe3);

            float oA = sb4, oB = sb4;
#pragma unroll
            for (int k = 0; k < 8; k++) { oA = fmaf(h3A[k], sW4[k], oA);
                                          oB = fmaf(h3B[k], sW4[k], oB); }
            *(float2*)(out + e0) = make_float2(oA, oB);
        } else {
            // ---- scalar tail (only when E is odd) ----
            int s, d;
            if (is64) { s = ei[2 * (size_t)e0]; d = ei[2 * ((size_t)E + e0)]; }
            else      { s = ei[e0];             d = ei[(size_t)E + e0]; }
            const float4* ap = (const float4*)(g_xs + (size_t)s * 8);
            const float4* bp = (const float4*)(g_xb + (size_t)d * 8);
            float4 a0 = ap[0], a1 = ap[1], c0 = bp[0], c1 = bp[1];
            float h[8] = { a0.x + c0.x, a0.y + c0.y, a0.z + c0.z, a0.w + c0.w,
                           a1.x + c1.x, a1.y + c1.y, a1.z + c1.z, a1.w + c1.w };
            ln_tanh(h, sg1, sbe1);
            float h2[8]; gemm8(h, h2, sW2, sb2);
            ln_tanh(h2, sg2, sbe2);
            float h3[8]; gemm8(h2, h3, sW3, sb3);
            ln_tanh(h3, sg3, sbe3);
            float o = sb4;
#pragma unroll
            for (int k = 0; k < 8; k++) o = fmaf(h3[k], sW4[k], o);
            out[e0] = o;
        }
    }
}

// ---------------------------------------------------------------------------
extern "C" void kernel_launch(void* const* d_in, const int* in_sizes, int n_in,
                              void* d_out, int out_size)
{
    const float* x     = (const float*)d_in[0];
    const int*   ei    = (const int*)d_in[1];
    const float* vp    = (const float*)d_in[2];
    const int*   batch = (const int*)d_in[3];
    const float* W1  = (const float*)d_in[4];
    const float* b1  = (const float*)d_in[5];
    const float* g1  = (const float*)d_in[6];
    const float* be1 = (const float*)d_in[7];
    const float* W2  = (const float*)d_in[8];
    const float* b2  = (const float*)d_in[9];
    const float* g2  = (const float*)d_in[10];
    const float* be2 = (const float*)d_in[11];
    const float* W3  = (const float*)d_in[12];
    const float* b3  = (const float*)d_in[13];
    const float* g3  = (const float*)d_in[14];
    const float* be3 = (const float*)d_in[15];
    const float* W4  = (const float*)d_in[16];
    const float* b4  = (const float*)d_in[17];

    int N = in_sizes[0] / 16;
    int E = in_sizes[1] / 2;
    int G = in_sizes[2] / 16;

    int pb = (N + 255) / 256;
    pre_k<<<pb, 256>>>(x, batch, vp, W1, b1, ei, N, G);

    // 2 edges/thread, ~5 pairs per thread via grid-stride
    int eb = 2368;
    long long need = ((long long)E / 2 + 127) / 128;
    if (need < eb) eb = (int)need;
    edge_k<<<eb, 128>>>(ei, E, g1, be1, W2, b2, g2, be2, W3, b3, g3, be3,
                        W4, b4, (float*)d_out);
}